// round 1
// baseline (speedup 1.0000x reference)
#include <cuda_runtime.h>
#include <math.h>

#define BATCH   8
#define INCH    32
#define OUTCH   32
#define TLEN    4096
#define NP      128        // conjugate pairs (state dim 256 -> 128 pairs)
#define CL      64         // chunk length
#define NCHUNK  (TLEN / CL)  // 64

// ---- device scratch (no allocations allowed) ----
__device__ float g_Ar[NP], g_Ai[NP], g_fr[NP], g_fi[NP], g_ALr[NP], g_ALi[NP];
__device__ float g_w[BATCH * TLEN * NP];                   // 16 MB, [b][t][p]
__device__ float g_endr[BATCH * NCHUNK * NP], g_endi[BATCH * NCHUNK * NP];
__device__ float g_sr[BATCH * NCHUNK * NP],  g_si[BATCH * NCHUNK * NP];

// ---- K1: per-pair parameters -------------------------------------------
// lam = -softplus(raw_lambda) + i*raw_omega ; A_d = exp(lam) ;
// factor = (A_d - 1)/lam (|lam|>eps else DT=1) ; AL = A_d^CL
__global__ void k_params(const float* __restrict__ raw_lambda,
                         const float* __restrict__ raw_omega) {
    int p = threadIdx.x;
    if (p >= NP) return;
    float x  = raw_lambda[p];
    float sp = fmaxf(x, 0.f) + log1pf(expf(-fabsf(x)));   // softplus, jax-style
    float lr = -sp;
    float li = raw_omega[p];
    float er = expf(lr);
    float Ar = er * cosf(li);
    float Ai = er * sinf(li);
    float m2 = lr * lr + li * li;
    float fr, fi;
    if (sqrtf(m2) > 1e-6f) {
        float nr = Ar - 1.f, ni = Ai;
        fr = (nr * lr + ni * li) / m2;
        fi = (ni * lr - nr * li) / m2;
    } else {
        fr = 1.0f; fi = 0.f;                               // DT = 1
    }
    g_Ar[p] = Ar; g_Ai[p] = Ai; g_fr[p] = fr; g_fi[p] = fi;
    float eL = expf(lr * (float)CL);
    g_ALr[p] = eL * cosf(li * (float)CL);
    g_ALi[p] = eL * sinf(li * (float)CL);
}

// ---- K2: per-(batch,chunk): w = Bc^T u  (store), chunk-local recurrence ----
__global__ __launch_bounds__(256) void k_chunk(const float* __restrict__ u,
                                               const float* __restrict__ Bc) {
    __shared__ float u_sm[INCH * CL];    // [i][t]   8 KB
    __shared__ float w_sm[CL * NP];      // [t][p]  32 KB
    int c = blockIdx.x, b = blockIdx.y;
    int t0 = c * CL;
    int tid = threadIdx.x;

    // stage u tile (coalesced rows of 64)
    for (int idx = tid; idx < INCH * CL; idx += 256) {
        int i = idx >> 6, t = idx & 63;
        u_sm[idx] = u[(b * INCH + i) * TLEN + t0 + t];
    }
    __syncthreads();

    // w GEMM: thread -> (p = tid&127, half th = tid>>7), 32 contiguous t each
    int p  = tid & 127;
    int th = tid >> 7;
    float acc[32];
#pragma unroll
    for (int k = 0; k < 32; k++) acc[k] = 0.f;
#pragma unroll 8
    for (int i = 0; i < INCH; i++) {
        float bb = __ldg(&Bc[i * NP + p]);                 // coalesced across lanes
        const float4* urow = (const float4*)&u_sm[i * CL + th * 32];  // broadcast
#pragma unroll
        for (int k4 = 0; k4 < 8; k4++) {
            float4 uv = urow[k4];
            acc[4 * k4 + 0] = fmaf(bb, uv.x, acc[4 * k4 + 0]);
            acc[4 * k4 + 1] = fmaf(bb, uv.y, acc[4 * k4 + 1]);
            acc[4 * k4 + 2] = fmaf(bb, uv.z, acc[4 * k4 + 2]);
            acc[4 * k4 + 3] = fmaf(bb, uv.w, acc[4 * k4 + 3]);
        }
    }
    int base = (b * TLEN + t0) * NP;
#pragma unroll
    for (int k = 0; k < 32; k++) {
        int t = th * 32 + k;
        w_sm[t * NP + p]       = acc[k];
        g_w[base + t * NP + p] = acc[k];                   // coalesced (p inner)
    }
    __syncthreads();

    // chunk-local recurrence, zero init -> local end state
    if (tid < NP) {
        float Ar = g_Ar[tid], Ai = g_Ai[tid], fr = g_fr[tid], fi = g_fi[tid];
        float xr = 0.f, xi = 0.f;
#pragma unroll 8
        for (int t = 0; t < CL; t++) {
            float w  = w_sm[t * NP + tid];
            float nr = fmaf(Ar, xr, fmaf(-Ai, xi, fr * w));
            float ni = fmaf(Ai, xr, fmaf( Ar, xi, fi * w));
            xr = nr; xi = ni;
        }
        int o = (b * NCHUNK + c) * NP + tid;
        g_endr[o] = xr; g_endi[o] = xi;
    }
}

// ---- K3: exact inter-chunk scan: s[c+1] = A^L s[c] + end[c] -------------
__global__ void k_scan() {
    int tid = threadIdx.x;          // 1024 = 8 batches * 128 pairs
    int b = tid >> 7, p = tid & 127;
    float ALr = g_ALr[p], ALi = g_ALi[p];
    float xr = 0.f, xi = 0.f;
#pragma unroll 8
    for (int c = 0; c < NCHUNK; c++) {
        int o = (b * NCHUNK + c) * NP + p;
        g_sr[o] = xr; g_si[o] = xi;
        float er = g_endr[o], ei = g_endi[o];     // hoisted by unroll -> MLP
        float nr = fmaf(ALr, xr, fmaf(-ALi, xi, er));
        float ni = fmaf(ALi, xr, fmaf( ALr, xi, ei));
        xr = nr; xi = ni;
    }
}

// ---- K4: per-(batch,chunk): exact recurrence from s, then y = 2 C^T xr ----
__global__ __launch_bounds__(256) void k_out(const float* __restrict__ C,
                                             float* __restrict__ y) {
    __shared__ float x_sm[CL * NP];          // 32 KB: w tile, then xr tile
    __shared__ float y_sm[CL * (OUTCH + 1)]; // transpose pad (8.25 KB)
    int c = blockIdx.x, b = blockIdx.y;
    int t0 = c * CL;
    int tid = threadIdx.x;

    int base = (b * TLEN + t0) * NP;
    for (int idx = tid; idx < CL * NP; idx += 256)
        x_sm[idx] = g_w[base + idx];
    __syncthreads();

    // recurrence with true initial state; overwrite w with Re(x)
    if (tid < NP) {
        int p = tid;
        float Ar = g_Ar[p], Ai = g_Ai[p], fr = g_fr[p], fi = g_fi[p];
        int so = (b * NCHUNK + c) * NP + p;
        float xr = g_sr[so], xi = g_si[so];
#pragma unroll 8
        for (int t = 0; t < CL; t++) {
            float w  = x_sm[t * NP + p];
            float nr = fmaf(Ar, xr, fmaf(-Ai, xi, fr * w));
            float ni = fmaf(Ai, xr, fmaf( Ar, xi, fi * w));
            xr = nr; xi = ni;
            x_sm[t * NP + p] = xr;
        }
    }
    __syncthreads();

    // output GEMM: thread -> (o = tid&31, tt = tid>>5), 8 t's strided by 8
    int o = tid & 31, tt = tid >> 5;
    float acc[8];
#pragma unroll
    for (int k = 0; k < 8; k++) acc[k] = 0.f;
#pragma unroll 4
    for (int p = 0; p < NP; p += 4) {
        float c0 = __ldg(&C[(p + 0) * OUTCH + o]);   // coalesced across lanes
        float c1 = __ldg(&C[(p + 1) * OUTCH + o]);
        float c2 = __ldg(&C[(p + 2) * OUTCH + o]);
        float c3 = __ldg(&C[(p + 3) * OUTCH + o]);
#pragma unroll
        for (int k = 0; k < 8; k++) {
            float4 xv = *(const float4*)&x_sm[(tt + 8 * k) * NP + p]; // broadcast
            acc[k] = fmaf(c0, xv.x, acc[k]);
            acc[k] = fmaf(c1, xv.y, acc[k]);
            acc[k] = fmaf(c2, xv.z, acc[k]);
            acc[k] = fmaf(c3, xv.w, acc[k]);
        }
    }
#pragma unroll
    for (int k = 0; k < 8; k++)
        y_sm[(tt + 8 * k) * (OUTCH + 1) + o] = 2.f * acc[k];
    __syncthreads();

    // coalesced y write via smem transpose
    for (int idx = tid; idx < OUTCH * CL; idx += 256) {
        int oo = idx >> 6, t = idx & 63;
        y[(b * OUTCH + oo) * TLEN + t0 + t] = y_sm[t * (OUTCH + 1) + oo];
    }
}

extern "C" void kernel_launch(void* const* d_in, const int* in_sizes, int n_in,
                              void* d_out, int out_size) {
    const float* u  = (const float*)d_in[0];
    const float* rl = (const float*)d_in[1];
    const float* ro = (const float*)d_in[2];
    const float* Bc = (const float*)d_in[3];   // (32, 128)
    const float* C  = (const float*)d_in[4];   // (128, 32)
    float* y = (float*)d_out;

    k_params<<<1, 128>>>(rl, ro);
    k_chunk<<<dim3(NCHUNK, BATCH), 256>>>(u, Bc);
    k_scan<<<1, 1024>>>();
    k_out<<<dim3(NCHUNK, BATCH), 256>>>(C, y);
}